// round 5
// baseline (speedup 1.0000x reference)
#include <cuda_runtime.h>
#include <math.h>

#define NTOK 100
#define XP   65
#define OTM  25
#define MP   26
#define NTHREADS 128

// smem layout (float units)
#define OFF_X    0        // X[100][65]
#define OFF_H    6500     // H[100][65]
#define OFF_QKV  13000    // QKV[100][20]
#define OFF_WBUF 15000    // wbuf[2720]
#define OFF_Y    17720    // Y[100][33]
#define OFF_KM   21020    // Km[100][26]
#define OFF_OTW  23620    // otw[800]
#define OFF_UU   24420    // uu[100]
#define OFF_VV   24520    // vv[28]
#define OFF_LA   24548    // la[100]
#define OFF_MSK  24648    // msk[100] int
#define OFF_CNT  24748
#define SMEM_FLOATS 24752
#define SMEM_BYTES  (SMEM_FLOATS * 4)

__global__ void __launch_bounds__(NTHREADS)
jc_struc_kernel(const float* __restrict__ jc,   const int* __restrict__ flg,
                const float* __restrict__ enc_w, const float* __restrict__ enc_b,
                const float* __restrict__ B_sig, const float* __restrict__ B_jid,
                const float* __restrict__ qkv_w, const float* __restrict__ out_w,
                const float* __restrict__ out_b, const float* __restrict__ ln1_s,
                const float* __restrict__ ln1_b, const float* __restrict__ ln2_s,
                const float* __restrict__ ln2_b, const float* __restrict__ ff1_w,
                const float* __restrict__ ff1_b, const float* __restrict__ ff2_w,
                const float* __restrict__ ff2_b, const float* __restrict__ dec_w,
                const float* __restrict__ dec_b, const float* __restrict__ ot_w,
                float* __restrict__ out)
{
    extern __shared__ float sm[];
    float (*X)[XP]   = (float(*)[XP])(sm + OFF_X);
    float (*H)[XP]   = (float(*)[XP])(sm + OFF_H);
    float (*QKV)[20] = (float(*)[20])(sm + OFF_QKV);
    float* wbuf      = sm + OFF_WBUF;
    float (*Y)[33]   = (float(*)[33])(sm + OFF_Y);
    float* Km        = sm + OFF_KM;
    float* otw       = sm + OFF_OTW;
    float* uu        = sm + OFF_UU;
    float* vv        = sm + OFF_VV;
    float* la        = sm + OFF_LA;
    int*   msk       = (int*)(sm + OFF_MSK);
    float* cntp      = sm + OFF_CNT;

    const int tid = threadIdx.x;
    const int s   = blockIdx.x;
    const int t   = tid;            // token owned by this thread (if tid < 100)
    const float TWO_PI = 6.283185307179586f;
    const float INV_SQRT2 = 0.7071067811865476f;

    // ================= Embedding (one thread per token) =================
    if (t < NTOK) {
        const size_t base = ((size_t)s * NTOK + t) * 3;
        const float p0 = jc[base + 0], p1 = jc[base + 1], p2 = jc[base + 2];
        const float jd = (float)(t / 4);     // joint id: repeat(..., 4, axis=0)
        msk[t] = flg[(size_t)s * NTOK + t] > 0;
        for (int c = 0; c < 32; c++) {
            float proj = TWO_PI * (p0 * B_sig[c] + p1 * B_sig[32 + c] + p2 * B_sig[64 + c]);
            float ss, cs; sincosf(proj, &ss, &cs);
            float pj = TWO_PI * (jd * B_jid[c]);
            float sj, cj; sincosf(pj, &sj, &cj);
            X[t][c]      = (p0 * enc_w[c]      + p1 * enc_w[64 + c]      + p2 * enc_w[128 + c])      + enc_b[c]      + ss + sj;
            X[t][c + 32] = (p0 * enc_w[c + 32] + p1 * enc_w[64 + c + 32] + p2 * enc_w[128 + c + 32]) + enc_b[c + 32] + cs + cj;
        }
    }
    __syncthreads();
    if (tid == 0) {
        int c = 0;
        for (int i = 0; i < NTOK; i++) c += msk[i];
        *cntp = (float)c;
    }
    __syncthreads();

    // ================= Transformer layers =================
    for (int l = 0; l < 4; l++) {
        // --- Phase A weights: ln1_s@0, ln1_b@64, qkv (unpadded, stride 18) @128 ---
        for (int i = tid; i < 1280; i += NTHREADS) {
            float v;
            if (i < 64)        v = ln1_s[l * 64 + i];
            else if (i < 128)  v = ln1_b[l * 64 + (i - 64)];
            else               v = qkv_w[l * 1152 + (i - 128)];
            wbuf[i] = v;
        }
        __syncthreads();

        // --- LN1 -> H (per token, serial) ---
        if (t < NTOK) {
            float mu = 0.f;
            for (int d = 0; d < 64; d++) mu += X[t][d];
            mu /= 64.0f;
            float var = 0.f;
            for (int d = 0; d < 64; d++) { float dv = X[t][d] - mu; var += dv * dv; }
            var /= 64.0f;
            float rs = rsqrtf(var + 1e-5f);
            for (int d = 0; d < 64; d++)
                H[t][d] = (X[t][d] - mu) * rs * wbuf[d] + wbuf[64 + d];
        }
        __syncthreads();

        // --- QKV row (per token, serial, all 18 outputs) ---
        if (t < NTOK) {
            for (int c = 0; c < 18; c++) {
                float acc = 0.f;
                for (int k = 0; k < 64; k++)
                    acc += H[t][k] * wbuf[128 + k * 18 + c];
                QKV[t][c] = acc;
            }
        }
        __syncthreads();

        // --- Phase B weights: out_w@0 (384), out_b@384, ln2_s@448, ln2_b@512 ---
        for (int i = tid; i < 576; i += NTHREADS) {
            float v;
            if (i < 384)      v = out_w[l * 384 + i];
            else if (i < 448) v = out_b[l * 64 + (i - 384)];
            else if (i < 512) v = ln2_s[l * 64 + (i - 448)];
            else              v = ln2_b[l * 64 + (i - 512)];
            wbuf[i] = v;
        }

        // --- Attention (per token = query row; literal -1e9 masking) ---
        float o[6];
        if (t < NTOK) {
            for (int hh = 0; hh < 3; hh++) {
                const int qc = 2 * hh, kc = 6 + 2 * hh, vc = 12 + 2 * hh;
                float q0 = QKV[t][qc], q1 = QKV[t][qc + 1];
                float m = -3.0e38f;
                for (int j = 0; j < NTOK; j++) {
                    float sc = msk[j] ? ((q0 * QKV[j][kc] + q1 * QKV[j][kc + 1]) * INV_SQRT2) : -1e9f;
                    m = fmaxf(m, sc);
                }
                float den = 0.f, o0 = 0.f, o1 = 0.f;
                for (int j = 0; j < NTOK; j++) {
                    float sc = msk[j] ? ((q0 * QKV[j][kc] + q1 * QKV[j][kc + 1]) * INV_SQRT2) : -1e9f;
                    float e = expf(sc - m);
                    den += e;
                    o0 += e * QKV[j][vc];
                    o1 += e * QKV[j][vc + 1];
                }
                o[qc]     = o0 / den;
                o[qc + 1] = o1 / den;
            }
        }
        __syncthreads();   // phase B wbuf ready; QKV reads done

        // --- Out projection + residual; then LN2 -> H (per token, serial) ---
        if (t < NTOK) {
            for (int e = 0; e < 64; e++) {
                float acc = wbuf[384 + e];
                for (int c = 0; c < 6; c++)
                    acc += o[c] * wbuf[c * 64 + e];
                X[t][e] += acc;
            }
            float mu = 0.f;
            for (int d = 0; d < 64; d++) mu += X[t][d];
            mu /= 64.0f;
            float var = 0.f;
            for (int d = 0; d < 64; d++) { float dv = X[t][d] - mu; var += dv * dv; }
            var /= 64.0f;
            float rs = rsqrtf(var + 1e-5f);
            for (int d = 0; d < 64; d++)
                H[t][d] = (X[t][d] - mu) * rs * wbuf[448 + d] + wbuf[512 + d];
        }
        __syncthreads();

        // --- Phase C weights: ff1_w@0 (1024), ff1_b@1024 (16), ff2_w@1040 (1024), ff2_b@2064 (64) ---
        for (int i = tid; i < 2128; i += NTHREADS) {
            float v;
            if (i < 1024)      v = ff1_w[l * 1024 + i];
            else if (i < 1040) v = ff1_b[l * 16 + (i - 1024)];
            else if (i < 2064) v = ff2_w[l * 1024 + (i - 1040)];
            else               v = ff2_b[l * 64 + (i - 2064)];
            wbuf[i] = v;
        }
        __syncthreads();

        // --- FFN (per token, serial): X += gelu(H@ff1+b1)@ff2 + b2 ---
        if (t < NTOK) {
            float g[16];
            for (int c = 0; c < 16; c++) {
                float acc = wbuf[1024 + c];
                for (int k = 0; k < 64; k++)
                    acc += H[t][k] * wbuf[k * 16 + c];
                g[c] = 0.5f * acc * (1.0f + erff(acc * INV_SQRT2));
            }
            for (int e = 0; e < 64; e++) {
                float acc = wbuf[2064 + e];
                for (int c = 0; c < 16; c++)
                    acc += g[c] * wbuf[1040 + c * 64 + e];
                X[t][e] += acc;
            }
        }
        __syncthreads();
    }

    // ================= Decoder: Y = relu(X @ dec_w + dec_b) =================
    for (int i = tid; i < 2080; i += NTHREADS)
        wbuf[i] = (i < 2048) ? dec_w[i] : dec_b[i - 2048];
    __syncthreads();
    if (t < NTOK) {
        for (int c = 0; c < 32; c++) {
            float acc = wbuf[2048 + c];
            for (int k = 0; k < 64; k++)
                acc += X[t][k] * wbuf[k * 32 + c];
            Y[t][c] = fmaxf(acc, 0.f);
        }
    }
    __syncthreads();

    // ================= OT kernel: Km = (dot * filt) / 0.1 (log domain) =================
    // Band test, convention B: XLA algebraic-simplifier rewrites x/const ->
    // x * (1/const) BEFORE folding. pa = fl(i*fl(0.01)), pb = fl(j*fl(0.04)).
    for (int i = tid; i < 800; i += NTHREADS) otw[i] = ot_w[i];
    __syncthreads();
    for (int idx = tid; idx < NTOK * OTM; idx += NTHREADS) {
        int i = idx / OTM, j = idx % OTM;
        float pa = __fmul_rn((float)(i + 1), 0.00999999977648258209228515625f); // fl32(1/100)
        float pb = __fmul_rn((float)(j + 1), 0.039999999105930328369140625f);   // fl32(1/25)
        float filt = (fabsf(__fsub_rn(pa, pb)) < 0.1f) ? 1.0f : 0.0f;
        float dot = 0.f;
        for (int d = 0; d < 32; d++) dot += Y[i][d] * otw[j * 32 + d];
        Km[i * MP + j] = __fdiv_rn(dot * filt, 0.1f);
    }
    if (t < NTOK)
        la[t] = msk[t] ? -logf(*cntp) : -1e9f;
    if (tid < OTM) vv[tid] = 0.0f;
    __syncthreads();

    // ================= Log-domain Sinkhorn (fp32), 100 iterations =================
    const float LOG_B = -3.2188758248682006f;   // -log(25)
    for (int it = 0; it < 100; it++) {
        if (t < NTOK) {
            float mx = -3.0e38f;
            for (int j = 0; j < OTM; j++) mx = fmaxf(mx, Km[t * MP + j] + vv[j]);
            float sacc = 0.f;
            for (int j = 0; j < OTM; j++) sacc += expf(Km[t * MP + j] + vv[j] - mx);
            uu[t] = la[t] - (logf(sacc) + mx);
        }
        __syncthreads();
        {
            int j = tid >> 2; if (j > 24) j = 24;
            int sg = tid & 3;
            float mx = -3.0e38f;
            for (int i = sg; i < NTOK; i += 4) mx = fmaxf(mx, Km[i * MP + j] + uu[i]);
            mx = fmaxf(mx, __shfl_xor_sync(0xffffffffu, mx, 1));
            mx = fmaxf(mx, __shfl_xor_sync(0xffffffffu, mx, 2));
            float sacc = 0.f;
            for (int i = sg; i < NTOK; i += 4) sacc += expf(Km[i * MP + j] + uu[i] - mx);
            sacc += __shfl_xor_sync(0xffffffffu, sacc, 1);
            sacc += __shfl_xor_sync(0xffffffffu, sacc, 2);
            if (sg == 0 && tid < 100) vv[j] = LOG_B - (logf(sacc) + mx);
        }
        __syncthreads();
    }

    // T = exp(K + u + v) in place
    for (int idx = tid; idx < NTOK * OTM; idx += NTHREADS) {
        int i = idx / OTM, j = idx % OTM;
        Km[i * MP + j] = expf(Km[i * MP + j] + uu[i] + vv[j]);
    }
    __syncthreads();

    // ================= Output: out[s,m,d] = 25 * sum_i T[i][m] * Y[i][d] =================
    for (int idx = tid; idx < OTM * 32; idx += NTHREADS) {
        int m = idx >> 5, d = idx & 31;
        float acc = 0.f;
        for (int i = 0; i < NTOK; i++)
            acc += Km[i * MP + m] * Y[i][d];
        out[((size_t)s * OTM + m) * 32 + d] = acc * 25.0f;
    }
}

extern "C" void kernel_launch(void* const* d_in, const int* in_sizes, int n_in,
                              void* d_out, int out_size)
{
    (void)in_sizes; (void)n_in; (void)out_size;
    const float* jc    = (const float*)d_in[0];
    const int*   flg   = (const int*)  d_in[1];
    const float* enc_w = (const float*)d_in[2];
    const float* enc_b = (const float*)d_in[3];
    const float* B_sig = (const float*)d_in[4];
    const float* B_jid = (const float*)d_in[5];
    const float* qkv_w = (const float*)d_in[6];
    const float* out_w = (const float*)d_in[7];
    const float* out_b = (const float*)d_in[8];
    const float* ln1_s = (const float*)d_in[9];
    const float* ln1_b = (const float*)d_in[10];
    const float* ln2_s = (const float*)d_in[11];
    const float* ln2_b = (const float*)d_in[12];
    const float* ff1_w = (const float*)d_in[13];
    const float* ff1_b = (const float*)d_in[14];
    const float* ff2_w = (const float*)d_in[15];
    const float* ff2_b = (const float*)d_in[16];
    const float* dec_w = (const float*)d_in[17];
    const float* dec_b = (const float*)d_in[18];
    const float* ot_w  = (const float*)d_in[19];
    float* out = (float*)d_out;

    cudaFuncSetAttribute(jc_struc_kernel,
                         cudaFuncAttributeMaxDynamicSharedMemorySize, SMEM_BYTES);
    jc_struc_kernel<<<800, NTHREADS, SMEM_BYTES>>>(
        jc, flg, enc_w, enc_b, B_sig, B_jid, qkv_w, out_w, out_b,
        ln1_s, ln1_b, ln2_s, ln2_b, ff1_w, ff1_b, ff2_w, ff2_b,
        dec_w, dec_b, ot_w, out);
}

// round 6
// speedup vs baseline: 1.8237x; 1.8237x over previous
#include <cuda_runtime.h>
#include <math.h>

#define NTOK 100
#define XP   65
#define OTM  25
#define MP   26
#define NTHREADS 128

// smem layout (float units)
#define OFF_X    0        // X[100][65]; after decoder: Km[100][26] @0, otw[800] @2600
#define OFF_HY   6500     // H[100][65] during transformer; Y[100][33] after
#define OFF_QKV  13000    // QKV[100][20]
#define OFF_WBUF 15000    // wbuf[2720]
#define OFF_UU   17728    // uu[100]
#define OFF_VV   17828    // vv[28]
#define OFF_AA   17856    // aa[100]
#define OFF_MSK  17956    // msk[100] int
#define OFF_CNT  18056
#define SMEM_FLOATS 18060
#define SMEM_BYTES  (SMEM_FLOATS * 4)

__global__ void __launch_bounds__(NTHREADS)
jc_struc_kernel(const float* __restrict__ jc,   const int* __restrict__ flg,
                const float* __restrict__ enc_w, const float* __restrict__ enc_b,
                const float* __restrict__ B_sig, const float* __restrict__ B_jid,
                const float* __restrict__ qkv_w, const float* __restrict__ out_w,
                const float* __restrict__ out_b, const float* __restrict__ ln1_s,
                const float* __restrict__ ln1_b, const float* __restrict__ ln2_s,
                const float* __restrict__ ln2_b, const float* __restrict__ ff1_w,
                const float* __restrict__ ff1_b, const float* __restrict__ ff2_w,
                const float* __restrict__ ff2_b, const float* __restrict__ dec_w,
                const float* __restrict__ dec_b, const float* __restrict__ ot_w,
                float* __restrict__ out)
{
    extern __shared__ float sm[];
    float (*X)[XP]   = (float(*)[XP])(sm + OFF_X);
    float (*H)[XP]   = (float(*)[XP])(sm + OFF_HY);
    float (*Y)[33]   = (float(*)[33])(sm + OFF_HY);
    float (*QKV)[20] = (float(*)[20])(sm + OFF_QKV);
    float* wbuf      = sm + OFF_WBUF;
    float* Km        = sm + OFF_X;          // aliases dead X after decoder
    float* otw       = sm + OFF_X + 2600;   // aliases dead X after decoder
    float* uu        = sm + OFF_UU;
    float* vv        = sm + OFF_VV;
    float* aa        = sm + OFF_AA;
    int*   msk       = (int*)(sm + OFF_MSK);
    float* cntp      = sm + OFF_CNT;

    const int tid = threadIdx.x;
    const int s   = blockIdx.x;
    const int t   = tid;            // token owned by this thread (if tid < 100)
    const float TWO_PI = 6.283185307179586f;
    const float INV_SQRT2 = 0.7071067811865476f;

    // ================= Embedding (one thread per token) =================
    if (t < NTOK) {
        const size_t base = ((size_t)s * NTOK + t) * 3;
        const float p0 = jc[base + 0], p1 = jc[base + 1], p2 = jc[base + 2];
        const float jd = (float)(t / 4);
        msk[t] = flg[(size_t)s * NTOK + t] > 0;
        #pragma unroll 4
        for (int c = 0; c < 32; c++) {
            float proj = TWO_PI * (p0 * B_sig[c] + p1 * B_sig[32 + c] + p2 * B_sig[64 + c]);
            float ss, cs; sincosf(proj, &ss, &cs);
            float pj = TWO_PI * (jd * B_jid[c]);
            float sj, cj; sincosf(pj, &sj, &cj);
            X[t][c]      = (p0 * enc_w[c]      + p1 * enc_w[64 + c]      + p2 * enc_w[128 + c])      + enc_b[c]      + ss + sj;
            X[t][c + 32] = (p0 * enc_w[c + 32] + p1 * enc_w[64 + c + 32] + p2 * enc_w[128 + c + 32]) + enc_b[c + 32] + cs + cj;
        }
    }
    __syncthreads();
    if (tid == 0) {
        int c = 0;
        for (int i = 0; i < NTOK; i++) c += msk[i];
        *cntp = 1.0f / (float)c;
    }
    __syncthreads();

    // ================= Transformer layers =================
    for (int l = 0; l < 4; l++) {
        // --- Phase A weights: ln1_s@0, ln1_b@64, qkv (stride 18) @128 ---
        for (int i = tid; i < 1280; i += NTHREADS) {
            float v;
            if (i < 64)        v = ln1_s[l * 64 + i];
            else if (i < 128)  v = ln1_b[l * 64 + (i - 64)];
            else               v = qkv_w[l * 1152 + (i - 128)];
            wbuf[i] = v;
        }
        __syncthreads();

        // --- LN1 (fused 2-pass) + QKV matmul (acc-register ordering) ---
        if (t < NTOK) {
            float ssum = 0.f, sq = 0.f;
            #pragma unroll 8
            for (int d = 0; d < 64; d++) { float v = X[t][d]; ssum += v; sq += v * v; }
            float mu = ssum * (1.0f / 64.0f);
            float var = sq * (1.0f / 64.0f) - mu * mu;
            float rs = rsqrtf(var + 1e-5f);
            #pragma unroll 8
            for (int d = 0; d < 64; d++)
                H[t][d] = (X[t][d] - mu) * rs * wbuf[d] + wbuf[64 + d];

            float acc[18];
            #pragma unroll
            for (int c = 0; c < 18; c++) acc[c] = 0.f;
            for (int k = 0; k < 64; k++) {
                float hv = H[t][k];
                const float* wr = wbuf + 128 + k * 18;
                #pragma unroll
                for (int c = 0; c < 18; c++) acc[c] += hv * wr[c];
            }
            #pragma unroll
            for (int c = 0; c < 18; c++) QKV[t][c] = acc[c];
        }
        __syncthreads();

        // --- Phase B weights: out_w@0 (384), out_b@384, ln2_s@448, ln2_b@512 ---
        for (int i = tid; i < 576; i += NTHREADS) {
            float v;
            if (i < 384)      v = out_w[l * 384 + i];
            else if (i < 448) v = out_b[l * 64 + (i - 384)];
            else if (i < 512) v = ln2_s[l * 64 + (i - 448)];
            else              v = ln2_b[l * 64 + (i - 512)];
            wbuf[i] = v;
        }

        // --- Attention: all 3 heads in merged passes (skip masked keys) ---
        float o[6];
        if (t < NTOK) {
            float q0 = QKV[t][0], q1 = QKV[t][1], q2 = QKV[t][2];
            float q3 = QKV[t][3], q4 = QKV[t][4], q5 = QKV[t][5];
            float m0 = -3.0e38f, m1 = -3.0e38f, m2 = -3.0e38f;
            for (int j = 0; j < NTOK; j++) {
                if (msk[j]) {
                    float s0 = (q0 * QKV[j][6]  + q1 * QKV[j][7])  * INV_SQRT2;
                    float s1 = (q2 * QKV[j][8]  + q3 * QKV[j][9])  * INV_SQRT2;
                    float s2 = (q4 * QKV[j][10] + q5 * QKV[j][11]) * INV_SQRT2;
                    m0 = fmaxf(m0, s0); m1 = fmaxf(m1, s1); m2 = fmaxf(m2, s2);
                }
            }
            float d0 = 0.f, d1 = 0.f, d2 = 0.f;
            float a0 = 0.f, a1 = 0.f, a2 = 0.f, a3 = 0.f, a4 = 0.f, a5 = 0.f;
            for (int j = 0; j < NTOK; j++) {
                if (msk[j]) {
                    float s0 = (q0 * QKV[j][6]  + q1 * QKV[j][7])  * INV_SQRT2;
                    float s1 = (q2 * QKV[j][8]  + q3 * QKV[j][9])  * INV_SQRT2;
                    float s2 = (q4 * QKV[j][10] + q5 * QKV[j][11]) * INV_SQRT2;
                    float e0 = __expf(s0 - m0), e1 = __expf(s1 - m1), e2 = __expf(s2 - m2);
                    d0 += e0; d1 += e1; d2 += e2;
                    a0 += e0 * QKV[j][12]; a1 += e0 * QKV[j][13];
                    a2 += e1 * QKV[j][14]; a3 += e1 * QKV[j][15];
                    a4 += e2 * QKV[j][16]; a5 += e2 * QKV[j][17];
                }
            }
            o[0] = a0 / d0; o[1] = a1 / d0;
            o[2] = a2 / d1; o[3] = a3 / d1;
            o[4] = a4 / d2; o[5] = a5 / d2;
        }
        __syncthreads();

        // --- Out projection + residual; LN2 (fused) -> H ---
        if (t < NTOK) {
            for (int e = 0; e < 64; e++) {
                float acc = wbuf[384 + e];
                #pragma unroll
                for (int c = 0; c < 6; c++) acc += o[c] * wbuf[c * 64 + e];
                X[t][e] += acc;
            }
            float ssum = 0.f, sq = 0.f;
            #pragma unroll 8
            for (int d = 0; d < 64; d++) { float v = X[t][d]; ssum += v; sq += v * v; }
            float mu = ssum * (1.0f / 64.0f);
            float var = sq * (1.0f / 64.0f) - mu * mu;
            float rs = rsqrtf(var + 1e-5f);
            #pragma unroll 8
            for (int d = 0; d < 64; d++)
                H[t][d] = (X[t][d] - mu) * rs * wbuf[448 + d] + wbuf[512 + d];
        }
        __syncthreads();

        // --- Phase C weights: ff1_w@0, ff1_b@1024, ff2_w@1040, ff2_b@2064 ---
        for (int i = tid; i < 2128; i += NTHREADS) {
            float v;
            if (i < 1024)      v = ff1_w[l * 1024 + i];
            else if (i < 1040) v = ff1_b[l * 16 + (i - 1024)];
            else if (i < 2064) v = ff2_w[l * 1024 + (i - 1040)];
            else               v = ff2_b[l * 64 + (i - 2064)];
            wbuf[i] = v;
        }
        __syncthreads();

        // --- FFN: X += gelu(H@ff1+b1)@ff2 + b2 (acc-register ordering) ---
        if (t < NTOK) {
            float g[16];
            #pragma unroll
            for (int c = 0; c < 16; c++) g[c] = wbuf[1024 + c];
            for (int k = 0; k < 64; k++) {
                float hv = H[t][k];
                const float* wr = wbuf + k * 16;
                #pragma unroll
                for (int c = 0; c < 16; c++) g[c] += hv * wr[c];
            }
            #pragma unroll
            for (int c = 0; c < 16; c++)
                g[c] = 0.5f * g[c] * (1.0f + erff(g[c] * INV_SQRT2));
            for (int e = 0; e < 64; e++) {
                float acc = wbuf[2064 + e];
                #pragma unroll
                for (int c = 0; c < 16; c++) acc += g[c] * wbuf[1040 + c * 64 + e];
                X[t][e] += acc;
            }
        }
        __syncthreads();
    }

    // ================= Decoder: Y = relu(X @ dec_w + dec_b) =================
    for (int i = tid; i < 2080; i += NTHREADS)
        wbuf[i] = (i < 2048) ? dec_w[i] : dec_b[i - 2048];
    __syncthreads();
    if (t < NTOK) {
        float acc[32];
        #pragma unroll
        for (int c = 0; c < 32; c++) acc[c] = wbuf[2048 + c];
        for (int k = 0; k < 64; k++) {
            float xv = X[t][k];
            const float* wr = wbuf + k * 32;
            #pragma unroll
            for (int c = 0; c < 32; c++) acc[c] += xv * wr[c];
        }
        #pragma unroll
        for (int c = 0; c < 32; c++) Y[t][c] = fmaxf(acc[c], 0.f);
    }
    __syncthreads();   // X now dead; Km/otw may overwrite it

    // ================= OT kernel (convention-B band test) =================
    for (int i = tid; i < 800; i += NTHREADS) otw[i] = ot_w[i];
    __syncthreads();
    for (int idx = tid; idx < NTOK * OTM; idx += NTHREADS) {
        int i = idx / OTM, j = idx % OTM;
        float pa = __fmul_rn((float)(i + 1), 0.00999999977648258209228515625f); // fl32(1/100)
        float pb = __fmul_rn((float)(j + 1), 0.039999999105930328369140625f);   // fl32(1/25)
        float filt = (fabsf(__fsub_rn(pa, pb)) < 0.1f) ? 1.0f : 0.0f;
        float dot = 0.f;
        #pragma unroll 8
        for (int d = 0; d < 32; d++) dot += Y[i][d] * otw[j * 32 + d];
        Km[i * MP + j] = __fdiv_rn(dot * filt, 0.1f);
    }
    __syncthreads();

    // Row-max rescale: M = exp(K - r_i); linear marginals
    if (t < NTOK) {
        float r = -3.0e38f;
        #pragma unroll
        for (int j = 0; j < OTM; j++) r = fmaxf(r, Km[t * MP + j]);
        #pragma unroll
        for (int j = 0; j < OTM; j++) Km[t * MP + j] = __expf(Km[t * MP + j] - r);
        aa[t] = msk[t] ? (*cntp) : 0.0f;
    }
    if (tid < OTM) vv[tid] = 1.0f;
    __syncthreads();

    // ================= Linear-domain Sinkhorn, 100 iterations =================
    for (int it = 0; it < 100; it++) {
        if (t < NTOK) {
            float sacc = 0.f;
            #pragma unroll
            for (int j = 0; j < OTM; j++) sacc += Km[t * MP + j] * vv[j];
            uu[t] = aa[t] / sacc;
        }
        __syncthreads();
        {
            int j = tid >> 2; if (j > 24) j = 24;
            int sg = tid & 3;
            float sacc = 0.f;
            #pragma unroll 5
            for (int i = sg; i < NTOK; i += 4) sacc += Km[i * MP + j] * uu[i];
            sacc += __shfl_xor_sync(0xffffffffu, sacc, 1);
            sacc += __shfl_xor_sync(0xffffffffu, sacc, 2);
            if (sg == 0 && tid < 100) vv[j] = 0.04f / sacc;
        }
        __syncthreads();
    }

    // Fold u into M: W[i][j] = M[i][j] * u_i
    for (int idx = tid; idx < NTOK * OTM; idx += NTHREADS) {
        int i = idx / OTM, j = idx % OTM;
        Km[i * MP + j] *= uu[i];
    }
    __syncthreads();

    // ================= Output: out[s,m,d] = 25 * v_m * sum_i W[i][m] * Y[i][d] ==========
    for (int idx = tid; idx < OTM * 32; idx += NTHREADS) {
        int m = idx >> 5, d = idx & 31;
        float acc = 0.f;
        #pragma unroll 4
        for (int i = 0; i < NTOK; i++)
            acc += Km[i * MP + m] * Y[i][d];
        out[((size_t)s * OTM + m) * 32 + d] = acc * (25.0f * vv[m]);
    }
}

extern "C" void kernel_launch(void* const* d_in, const int* in_sizes, int n_in,
                              void* d_out, int out_size)
{
    (void)in_sizes; (void)n_in; (void)out_size;
    const float* jc    = (const float*)d_in[0];
    const int*   flg   = (const int*)  d_in[1];
    const float* enc_w = (const float*)d_in[2];
    const float* enc_b = (const float*)d_in[3];
    const float* B_sig = (const float*)d_in[4];
    const float* B_jid = (const float*)d_in[5];
    const float* qkv_w = (const float*)d_in[6];
    const float* out_w = (const float*)d_in[7];
    const float* out_b = (const float*)d_in[8];
    const float* ln1_s = (const float*)d_in[9];
    const float* ln1_b = (const float*)d_in[10];
    const float* ln2_s = (const float*)d_in[11];
    const float* ln2_b = (const float*)d_in[12];
    const float* ff1_w = (const float*)d_in[13];
    const float* ff1_b = (const float*)d_in[14];
    const float* ff2_w = (const float*)d_in[15];
    const float* ff2_b = (const float*)d_in[16];
    const float* dec_w = (const float*)d_in[17];
    const float* dec_b = (const float*)d_in[18];
    const float* ot_w  = (const float*)d_in[19];
    float* out = (float*)d_out;

    cudaFuncSetAttribute(jc_struc_kernel,
                         cudaFuncAttributeMaxDynamicSharedMemorySize, SMEM_BYTES);
    jc_struc_kernel<<<800, NTHREADS, SMEM_BYTES>>>(
        jc, flg, enc_w, enc_b, B_sig, B_jid, qkv_w, out_w, out_b,
        ln1_s, ln1_b, ln2_s, ln2_b, ff1_w, ff1_b, ff2_w, ff2_b,
        dec_w, dec_b, ot_w, out);
}